// round 16
// baseline (speedup 1.0000x reference)
#include <cuda_runtime.h>
#include <cuda_bf16.h>
#include <cstdint>
#include <math.h>

#define B_   32
#define Q_   512
#define K_   512
#define H_   8
#define M_TOTAL (B_*Q_)
#define ACT_ELEMS (M_TOTAL*256)
#define ACT_U4  (ACT_ELEMS*2/16)
#define WT_U4   (5*256*256*2/16)

__device__ uint4 g_qd_hi[ACT_U4];
__device__ uint4 g_md_hi[ACT_U4];
__device__ uint4 g_wt_hi[WT_U4];
__device__ uint4 g_wt_lo[WT_U4];
// fp8 correction operands (activations + weights)
__device__ uint8_t g_qd8 [ACT_ELEMS];   // e4m3(A * 2^-4)
__device__ uint8_t g_qdl8[ACT_ELEMS];   // e5m2(Alo * 2^-4)
__device__ uint8_t g_md8 [ACT_ELEMS];
__device__ uint8_t g_mdl8[ACT_ELEMS];
__device__ uint8_t g_w8  [5*65536];     // e4m3(Whi * 2^4)
__device__ uint8_t g_wl8 [5*65536];     // e5m2(Wlo * 2^4)

__device__ uint32_t g_qh[M_TOTAL*128];
__device__ uint32_t g_ql[M_TOTAL*128];
__device__ uint32_t g_kh[M_TOTAL*128];
__device__ uint32_t g_kl[M_TOTAL*128];
__device__ uint32_t g_vh[M_TOTAL*128];
__device__ uint32_t g_vl[M_TOTAL*128];
__device__ float    g_gate[M_TOTAL*256];
__device__ uint32_t g_wah[M_TOTAL*128];
__device__ uint32_t g_wal[M_TOTAL*128];

__device__ __forceinline__ uint32_t smem_u32(const void* p) {
    uint32_t a;
    asm("{ .reg .u64 t; cvta.to.shared.u64 t, %1; cvt.u32.u64 %0, t; }" : "=r"(a) : "l"(p));
    return a;
}
__device__ __forceinline__ uint32_t pack2(float a, float b) {
    __nv_bfloat162 h = __floats2bfloat162_rn(a, b);
    return *(uint32_t*)&h;
}
__device__ __forceinline__ void split2(float x, float y, uint32_t& hi, uint32_t& lo) {
    __nv_bfloat16 bx = __float2bfloat16_rn(x), by = __float2bfloat16_rn(y);
    __nv_bfloat162 h2; h2.x = bx; h2.y = by;
    hi = *(uint32_t*)&h2;
    lo = pack2(x - __bfloat162float(bx), y - __bfloat162float(by));
}
__device__ __forceinline__ void split2f(float x, float y, uint32_t& hi, uint32_t& lo) {
    uint32_t xu = __float_as_uint(x), yu = __float_as_uint(y);
    hi = __byte_perm(xu, yu, 0x7632);
    float xh = __uint_as_float(xu & 0xFFFF0000u);
    float yh = __uint_as_float(yu & 0xFFFF0000u);
    lo = pack2(x - xh, y - yh);
}
__device__ __forceinline__ uint16_t cvt2_e4m3(float hi, float lo) {
    uint16_t r; asm("cvt.rn.satfinite.e4m3x2.f32 %0, %1, %2;" : "=h"(r) : "f"(hi), "f"(lo)); return r;
}
__device__ __forceinline__ uint16_t cvt2_e5m2(float hi, float lo) {
    uint16_t r; asm("cvt.rn.satfinite.e5m2x2.f32 %0, %1, %2;" : "=h"(r) : "f"(hi), "f"(lo)); return r;
}
// bytes v0,v1,v2,v3 in increasing address (k-order)
__device__ __forceinline__ uint32_t pack4_e4m3(float v0, float v1, float v2, float v3) {
    return (uint32_t)cvt2_e4m3(v1, v0) | ((uint32_t)cvt2_e4m3(v3, v2) << 16);
}
__device__ __forceinline__ uint32_t pack4_e5m2(float v0, float v1, float v2, float v3) {
    return (uint32_t)cvt2_e5m2(v1, v0) | ((uint32_t)cvt2_e5m2(v3, v2) << 16);
}
__device__ __forceinline__ void ldsm_x4(uint32_t& r0, uint32_t& r1, uint32_t& r2, uint32_t& r3, uint32_t addr) {
    asm volatile("ldmatrix.sync.aligned.m8n8.x4.shared.b16 {%0,%1,%2,%3}, [%4];"
                 : "=r"(r0), "=r"(r1), "=r"(r2), "=r"(r3) : "r"(addr));
}
__device__ __forceinline__ void ldsm_x4t(uint32_t& r0, uint32_t& r1, uint32_t& r2, uint32_t& r3, uint32_t addr) {
    asm volatile("ldmatrix.sync.aligned.m8n8.x4.trans.shared.b16 {%0,%1,%2,%3}, [%4];"
                 : "=r"(r0), "=r"(r1), "=r"(r2), "=r"(r3) : "r"(addr));
}
__device__ __forceinline__ void mma_bf16(float* c, const uint32_t* a, const uint32_t* b) {
    asm volatile("mma.sync.aligned.m16n8k16.row.col.f32.bf16.bf16.f32 "
                 "{%0,%1,%2,%3}, {%4,%5,%6,%7}, {%8,%9}, {%0,%1,%2,%3};"
                 : "+f"(c[0]), "+f"(c[1]), "+f"(c[2]), "+f"(c[3])
                 : "r"(a[0]), "r"(a[1]), "r"(a[2]), "r"(a[3]), "r"(b[0]), "r"(b[1]));
}
__device__ __forceinline__ void mma_e4e5(float* c, const uint32_t* a, const uint32_t* b) {
    asm volatile("mma.sync.aligned.m16n8k32.row.col.f32.e4m3.e5m2.f32 "
                 "{%0,%1,%2,%3}, {%4,%5,%6,%7}, {%8,%9}, {%0,%1,%2,%3};"
                 : "+f"(c[0]), "+f"(c[1]), "+f"(c[2]), "+f"(c[3])
                 : "r"(a[0]), "r"(a[1]), "r"(a[2]), "r"(a[3]), "r"(b[0]), "r"(b[1]));
}
__device__ __forceinline__ void mma_e5e4(float* c, const uint32_t* a, const uint32_t* b) {
    asm volatile("mma.sync.aligned.m16n8k32.row.col.f32.e5m2.e4m3.f32 "
                 "{%0,%1,%2,%3}, {%4,%5,%6,%7}, {%8,%9}, {%0,%1,%2,%3};"
                 : "+f"(c[0]), "+f"(c[1]), "+f"(c[2]), "+f"(c[3])
                 : "r"(a[0]), "r"(a[1]), "r"(a[2]), "r"(a[3]), "r"(b[0]), "r"(b[1]));
}
__device__ __forceinline__ void cp_async16(uint32_t dst, const void* src) {
    asm volatile("cp.async.cg.shared.global [%0], [%1], 16;" :: "r"(dst), "l"(src));
}
#define CP_COMMIT() asm volatile("cp.async.commit_group;" ::: "memory")
#define CP_WAIT(n)  asm volatile("cp.async.wait_group %0;" :: "n"(n) : "memory")

// ---------------- fused prep -------------------------------------------------
__global__ __launch_bounds__(256)
void prep_all(const float* __restrict__ q_data, const float* __restrict__ m_data,
              const float* __restrict__ qw, const float* __restrict__ kw,
              const float* __restrict__ vw, const float* __restrict__ gw,
              const float* __restrict__ ow)
{
    const int bid = blockIdx.x;
    const int t = threadIdx.x;
    if (bid < 8192) {
        int sel = bid >> 12;
        int i = (bid & 4095) * 256 + t;                // float4 index
        uint2* hi = (sel == 0) ? (uint2*)g_qd_hi : (uint2*)g_md_hi;
        uint32_t* a8  = (uint32_t*)((sel == 0) ? g_qd8  : g_md8);
        uint32_t* al8 = (uint32_t*)((sel == 0) ? g_qdl8 : g_mdl8);
        float4 v = ((const float4*)((sel == 0) ? q_data : m_data))[i];
        float h0 = __bfloat162float(__float2bfloat16_rn(v.x));
        float h1 = __bfloat162float(__float2bfloat16_rn(v.y));
        float h2 = __bfloat162float(__float2bfloat16_rn(v.z));
        float h3 = __bfloat162float(__float2bfloat16_rn(v.w));
        uint2 ho; ho.x = pack2(h0, h1); ho.y = pack2(h2, h3);
        hi[i] = ho;
        const float s = 0.0625f;                        // 2^-4
        a8[i]  = pack4_e4m3(v.x * s, v.y * s, v.z * s, v.w * s);
        al8[i] = pack4_e5m2((v.x - h0) * s, (v.y - h1) * s, (v.z - h2) * s, (v.w - h3) * s);
        return;
    }
    __shared__ float sm[64][65];
    const int wid = bid - 8192;
    const int z  = wid >> 4;
    const int kx = (wid >> 2) & 3;
    const int ny = wid & 3;
    const float* W = (z == 0) ? qw : (z == 1) ? kw : (z == 2) ? vw : (z == 3) ? gw : ow;
    const int k0 = kx * 64;
    const int n0 = ny * 64;
#pragma unroll
    for (int i = 0; i < 4; i++) {
        int idx = t + i * 256;
        int k = idx >> 4, n4 = idx & 15;
        float4 v = *(const float4*)&W[(size_t)(k0 + k) * 256 + n0 + n4 * 4];
        sm[n4 * 4 + 0][k] = v.x; sm[n4 * 4 + 1][k] = v.y;
        sm[n4 * 4 + 2][k] = v.z; sm[n4 * 4 + 3][k] = v.w;
    }
    __syncthreads();
    uint2* Hi = (uint2*)g_wt_hi;
    uint2* Lo = (uint2*)g_wt_lo;
#pragma unroll
    for (int i = 0; i < 4; i++) {
        int idx = t + i * 256;
        int n = idx >> 4, k4 = idx & 15;
        float a = sm[n][k4 * 4 + 0], b = sm[n][k4 * 4 + 1];
        float c = sm[n][k4 * 4 + 2], d = sm[n][k4 * 4 + 3];
        float ha = __bfloat162float(__float2bfloat16_rn(a));
        float hb = __bfloat162float(__float2bfloat16_rn(b));
        float hc = __bfloat162float(__float2bfloat16_rn(c));
        float hd = __bfloat162float(__float2bfloat16_rn(d));
        uint2 ho, lw;
        ho.x = pack2(ha, hb); ho.y = pack2(hc, hd);
        lw.x = pack2(a - ha, b - hb); lw.y = pack2(c - hc, d - hd);
        int eb = z * 65536 + (n0 + n) * 256 + k0 + k4 * 4;   // byte index
        Hi[eb >> 2] = ho; Lo[eb >> 2] = lw;
        ((uint32_t*)g_w8)[eb >> 2]  = pack4_e4m3(ha * 16.f, hb * 16.f, hc * 16.f, hd * 16.f);
        ((uint32_t*)g_wl8)[eb >> 2] = pack4_e5m2((a - ha) * 16.f, (b - hb) * 16.f,
                                                 (c - hc) * 16.f, (d - hd) * 16.f);
    }
}

// ---------------- projection GEMM: bf16 main + fp8 corrections --------------
#define AH8_OFF  0        // 128 x 80
#define A8_OFF   10240    // 128 x 48
#define AL8_OFF  16384
#define BH8_OFF  22528    // 128 x 80
#define B8_OFF   32768
#define BL8_OFF  38912
#define G8_STAGE 45056

__global__ __launch_bounds__(256, 2)
void gemm8_kernel(const float* __restrict__ gb)
{
    extern __shared__ __align__(128) char smg[];
    const uint32_t sb = smem_u32(smg);
    const int t = threadIdx.x, w = t >> 5, lane = t & 31;
    const int mw = w >> 1, nw = w & 1;
    const int mode = blockIdx.z;
    const int m0 = blockIdx.x * 128;
    const int n0 = blockIdx.y * 128;

    const uint4* Ah;
    const uint8_t *A8s, *AL8s;
    uint32_t *Oh = nullptr, *Ol = nullptr;
    float* Of = nullptr;
    if (mode == 0)      { Ah = g_qd_hi; A8s = g_qd8; AL8s = g_qdl8; Oh = g_qh; Ol = g_ql; }
    else if (mode == 1) { Ah = g_md_hi; A8s = g_md8; AL8s = g_mdl8; Oh = g_kh; Ol = g_kl; }
    else if (mode == 2) { Ah = g_md_hi; A8s = g_md8; AL8s = g_mdl8; Oh = g_vh; Ol = g_vl; }
    else                { Ah = g_qd_hi; A8s = g_qd8; AL8s = g_qdl8; Of = g_gate; }
    const uint4* Wh = g_wt_hi + mode * 8192;
    const uint8_t* B8s  = g_w8  + mode * 65536;
    const uint8_t* BL8s = g_wl8 + mode * 65536;

    auto stage = [&](int kc, int buf) {
        uint32_t base = sb + buf * G8_STAGE;
#pragma unroll
        for (int i = 0; i < 2; i++) {                 // A hi: 128 x 64B
            int idx = t + i * 256;
            int m = idx >> 2, k4 = idx & 3;
            cp_async16(base + AH8_OFF + m * 80 + k4 * 16,
                       Ah + (size_t)(m0 + m) * 32 + kc * 4 + k4);
        }
        { int m = t >> 1, k16 = t & 1;                // A8 / AL8: 128 x 32B each
          cp_async16(base + A8_OFF  + m * 48 + k16 * 16,
                     A8s  + (size_t)(m0 + m) * 256 + kc * 32 + k16 * 16);
          cp_async16(base + AL8_OFF + m * 48 + k16 * 16,
                     AL8s + (size_t)(m0 + m) * 256 + kc * 32 + k16 * 16); }
#pragma unroll
        for (int i = 0; i < 2; i++) {                 // B hi: 128 x 64B
            int idx = t + i * 256;
            int n = idx >> 2, k4 = idx & 3;
            cp_async16(base + BH8_OFF + n * 80 + k4 * 16,
                       Wh + (size_t)(n0 + n) * 32 + kc * 4 + k4);
        }
        { int n = t >> 1, k16 = t & 1;                // B8 / BL8
          cp_async16(base + B8_OFF  + n * 48 + k16 * 16,
                     B8s  + (size_t)(n0 + n) * 256 + kc * 32 + k16 * 16);
          cp_async16(base + BL8_OFF + n * 48 + k16 * 16,
                     BL8s + (size_t)(n0 + n) * 256 + kc * 32 + k16 * 16); }
        CP_COMMIT();
    };

    float c[2][8][4];
#pragma unroll
    for (int i = 0; i < 2; i++)
#pragma unroll
        for (int j = 0; j < 8; j++)
#pragma unroll
            for (int e = 0; e < 4; e++) c[i][j][e] = 0.f;

    stage(0, 0);
    stage(1, 1);
    CP_WAIT(1);
    __syncthreads();

    for (int kc = 0; kc < 8; kc++) {
        const uint32_t base = sb + (kc & 1) * G8_STAGE;
        // ---- main bf16 hi*hi -------------------------------------------------
#pragma unroll
        for (int ks = 0; ks < 2; ks++) {
            uint32_t ah[2][4];
#pragma unroll
            for (int mt = 0; mt < 2; mt++) {
                uint32_t roff = (uint32_t)(mw * 32 + mt * 16 + (lane & 15)) * 80 + ((lane >> 4) * 16) + ks * 32;
                ldsm_x4(ah[mt][0], ah[mt][1], ah[mt][2], ah[mt][3], base + AH8_OFF + roff);
            }
            uint32_t bh[8][2];
#pragma unroll
            for (int p = 0; p < 4; p++) {
                uint32_t nrow = (uint32_t)(nw * 64 + p * 16 + ((lane >> 4) << 3) + (lane & 7));
                uint32_t addr = nrow * 80 + ((lane >> 3) & 1) * 16 + ks * 32;
                uint32_t a0, a1, a2, a3;
                ldsm_x4(a0, a1, a2, a3, base + BH8_OFF + addr);
                bh[p * 2][0] = a0; bh[p * 2][1] = a1;
                bh[p * 2 + 1][0] = a2; bh[p * 2 + 1][1] = a3;
            }
#pragma unroll
            for (int mt = 0; mt < 2; mt++)
#pragma unroll
                for (int nt = 0; nt < 8; nt++)
                    mma_bf16(c[mt][nt], ah[mt], bh[nt]);
        }
        // ---- fp8 corrections (k=32 in one mma) --------------------------------
        {
            uint32_t a8f[2][4];
            uint32_t b8f[8][2];
            const uint32_t aro = (uint32_t)(mw * 32 + (lane & 15)) * 48 + ((lane >> 4) * 16);
            const uint32_t nro = (uint32_t)(nw * 64 + ((lane >> 4) << 3) + (lane & 7)) * 48 + ((lane >> 3) & 1) * 16;
            // pass2: e4m3(A*2^-4) x e5m2(Blo*2^4)
#pragma unroll
            for (int mt = 0; mt < 2; mt++)
                ldsm_x4(a8f[mt][0], a8f[mt][1], a8f[mt][2], a8f[mt][3],
                        base + A8_OFF + aro + mt * 16 * 48);
#pragma unroll
            for (int p = 0; p < 4; p++) {
                uint32_t a0, a1, a2, a3;
                ldsm_x4(a0, a1, a2, a3, base + BL8_OFF + nro + p * 16 * 48);
                b8f[p * 2][0] = a0; b8f[p * 2][1] = a1;
                b8f[p * 2 + 1][0] = a2; b8f[p * 2 + 1][1] = a3;
            }
#pragma unroll
            for (int mt = 0; mt < 2; mt++)
#pragma unroll
                for (int nt = 0; nt < 8; nt++)
                    mma_e4e5(c[mt][nt], a8f[mt], b8f[nt]);
            // pass3: e5m2(Alo*2^-4) x e4m3(Bhi*2^4)
#pragma unroll
            for (int mt = 0; mt < 2; mt++)
                ldsm_x4(a8f[mt][0], a8f[mt][1], a8f[mt][2], a8f[mt][3],
                        base + AL8_OFF + aro + mt * 16 * 48);
#pragma unroll
            for (int p = 0; p < 4; p++) {
                uint32_t a0, a1, a2, a3;
                ldsm_x4(a0, a1, a2, a3, base + B8_OFF + nro + p * 16 * 48);
                b8f[p * 2][0] = a0; b8f[p * 2][1] = a1;
                b8f[p * 2 + 1][0] = a2; b8f[p * 2 + 1][1] = a3;
            }
#pragma unroll
            for (int mt = 0; mt < 2; mt++)
#pragma unroll
                for (int nt = 0; nt < 8; nt++)
                    mma_e5e4(c[mt][nt], a8f[mt], b8f[nt]);
        }
        if (kc == 7) break;
        __syncthreads();
        if (kc + 2 < 8) { stage(kc + 2, kc & 1); CP_WAIT(1); }
        else            { CP_WAIT(0); }
        __syncthreads();
    }

    const float s_q = 0.17677669529663687f;
#pragma unroll
    for (int mt = 0; mt < 2; mt++) {
#pragma unroll
        for (int nt = 0; nt < 8; nt++) {
            int row = m0 + mw * 32 + mt * 16 + (lane >> 2);
            int col = n0 + nw * 64 + nt * 8 + (lane & 3) * 2;
            float2 v0 = make_float2(c[mt][nt][0], c[mt][nt][1]);
            float2 v1 = make_float2(c[mt][nt][2], c[mt][nt][3]);
            if (mode == 0) { v0.x *= s_q; v0.y *= s_q; v1.x *= s_q; v1.y *= s_q; }
            if (mode <= 2) {
                uint32_t h0, l0, h1, l1;
                split2(v0.x, v0.y, h0, l0);
                split2(v1.x, v1.y, h1, l1);
                Oh[(size_t)row * 128 + (col >> 1)] = h0;
                Ol[(size_t)row * 128 + (col >> 1)] = l0;
                Oh[(size_t)(row + 8) * 128 + (col >> 1)] = h1;
                Ol[(size_t)(row + 8) * 128 + (col >> 1)] = l1;
            } else {
                float2 g2 = *(const float2*)&gb[col];
                v0.x = 1.f / (1.f + __expf(-(v0.x + g2.x)));
                v0.y = 1.f / (1.f + __expf(-(v0.y + g2.y)));
                v1.x = 1.f / (1.f + __expf(-(v1.x + g2.x)));
                v1.y = 1.f / (1.f + __expf(-(v1.y + g2.y)));
                *(float2*)&Of[(size_t)row * 256 + col] = v0;
                *(float2*)&Of[(size_t)(row + 8) * 256 + col] = v1;
            }
        }
    }
}

// ---------------- out-proj GEMM (round-13 bf16 hi/lo, mode-4 only) ---------
#define AH_OFF 0
#define AL_OFF 10240
#define BH_OFF 20480
#define BL_OFF 30720
#define G_STAGE 40960

__global__ __launch_bounds__(256, 2)
void gemm_kernel(const float* __restrict__ ob, float* __restrict__ dout)
{
    extern __shared__ __align__(128) char smg[];
    const uint32_t sb = smem_u32(smg);
    const int t = threadIdx.x, w = t >> 5, lane = t & 31;
    const int mw = w >> 1, nw = w & 1;
    const int m0 = blockIdx.x * 128;
    const int n0 = blockIdx.y * 128;

    const uint4* Ah = (const uint4*)g_wah;
    const uint4* Al = (const uint4*)g_wal;
    const uint4* Wh = g_wt_hi + 4 * 8192;
    const uint4* Wl = g_wt_lo + 4 * 8192;

    auto stage = [&](int kc, int buf) {
        uint32_t base = sb + buf * G_STAGE;
#pragma unroll
        for (int i = 0; i < 4; i++) {
            int idx = t + i * 256;
            int comp = idx >> 9, rem = idx & 511;
            int m = rem >> 2, k4 = rem & 3;
            cp_async16(base + (comp ? AL_OFF : AH_OFF) + m * 80 + k4 * 16,
                       (comp ? Al : Ah) + (size_t)(m0 + m) * 32 + kc * 4 + k4);
        }
#pragma unroll
        for (int i = 0; i < 4; i++) {
            int idx = t + i * 256;
            int comp = idx >> 9, rem = idx & 511;
            int n = rem >> 2, k4 = rem & 3;
            cp_async16(base + (comp ? BL_OFF : BH_OFF) + n * 80 + k4 * 16,
                       (comp ? Wl : Wh) + (size_t)(n0 + n) * 32 + kc * 4 + k4);
        }
        CP_COMMIT();
    };

    float c[2][8][4];
#pragma unroll
    for (int i = 0; i < 2; i++)
#pragma unroll
        for (int j = 0; j < 8; j++)
#pragma unroll
            for (int e = 0; e < 4; e++) c[i][j][e] = 0.f;

    stage(0, 0);
    stage(1, 1);
    CP_WAIT(1);
    __syncthreads();

    for (int kc = 0; kc < 8; kc++) {
        const uint32_t base = sb + (kc & 1) * G_STAGE;
#pragma unroll
        for (int ks = 0; ks < 2; ks++) {
            uint32_t ah[2][4], al[2][4];
#pragma unroll
            for (int mt = 0; mt < 2; mt++) {
                uint32_t roff = (uint32_t)(mw * 32 + mt * 16 + (lane & 15)) * 80 + ((lane >> 4) * 16) + ks * 32;
                ldsm_x4(ah[mt][0], ah[mt][1], ah[mt][2], ah[mt][3], base + AH_OFF + roff);
                ldsm_x4(al[mt][0], al[mt][1], al[mt][2], al[mt][3], base + AL_OFF + roff);
            }
            uint32_t bh[8][2], bl[8][2];
#pragma unroll
            for (int p = 0; p < 4; p++) {
                uint32_t nrow = (uint32_t)(nw * 64 + p * 16 + ((lane >> 4) << 3) + (lane & 7));
                uint32_t addr = nrow * 80 + ((lane >> 3) & 1) * 16 + ks * 32;
                uint32_t a0, a1, a2, a3;
                ldsm_x4(a0, a1, a2, a3, base + BH_OFF + addr);
                bh[p * 2][0] = a0; bh[p * 2][1] = a1;
                bh[p * 2 + 1][0] = a2; bh[p * 2 + 1][1] = a3;
                ldsm_x4(a0, a1, a2, a3, base + BL_OFF + addr);
                bl[p * 2][0] = a0; bl[p * 2][1] = a1;
                bl[p * 2 + 1][0] = a2; bl[p * 2 + 1][1] = a3;
            }
#pragma unroll
            for (int mt = 0; mt < 2; mt++)
#pragma unroll
                for (int nt = 0; nt < 8; nt++) {
                    mma_bf16(c[mt][nt], ah[mt], bh[nt]);
                    mma_bf16(c[mt][nt], ah[mt], bl[nt]);
                    mma_bf16(c[mt][nt], al[mt], bh[nt]);
                }
        }
        if (kc == 7) break;
        __syncthreads();
        if (kc + 2 < 8) { stage(kc + 2, kc & 1); CP_WAIT(1); }
        else            { CP_WAIT(0); }
        __syncthreads();
    }

#pragma unroll
    for (int mt = 0; mt < 2; mt++) {
#pragma unroll
        for (int nt = 0; nt < 8; nt++) {
            int row = m0 + mw * 32 + mt * 16 + (lane >> 2);
            int col = n0 + nw * 64 + nt * 8 + (lane & 3) * 2;
            float2 g2 = *(const float2*)&ob[col];
            float2 v0 = make_float2(c[mt][nt][0] + g2.x, c[mt][nt][1] + g2.y);
            float2 v1 = make_float2(c[mt][nt][2] + g2.x, c[mt][nt][3] + g2.y);
            *(float2*)&dout[(size_t)row * 256 + col] = v0;
            *(float2*)&dout[(size_t)(row + 8) * 256 + col] = v1;
        }
    }
}

// ---------------- tensor-core flash attention (round-13 exact) -------------
#define QH_OFF 0
#define QL_OFF 10240
#define ST_BASE 20480
#define A_STAGE 20480

__global__ __launch_bounds__(256, 2)
void attn_kernel(const float* __restrict__ bias,
                 const float* __restrict__ nb)
{
    extern __shared__ __align__(128) char sma[];
    const uint32_t sb = smem_u32(sma);
    const int h  = blockIdx.x;
    const int q0 = blockIdx.y * 128;
    const int b  = blockIdx.z;
    const int t = threadIdx.x, w = t >> 5, lane = t & 31;

    const uint4* K4[4] = {(const uint4*)g_kh, (const uint4*)g_kl,
                          (const uint4*)g_vh, (const uint4*)g_vl};
    const uint32_t dstoff[4] = {0, 5120, 10240, 15360};

    auto stage_kv = [&](int kc, int buf) {
        uint32_t base = sb + ST_BASE + buf * A_STAGE;
        int r = t >> 2, k4 = t & 3;
#pragma unroll
        for (int i = 0; i < 4; i++)
            cp_async16(base + dstoff[i] + r * 80 + k4 * 16,
                       K4[i] + (size_t)(b * K_ + kc * 64 + r) * 32 + h * 4 + k4);
        CP_COMMIT();
    };

    {
        const uint4* Qh4 = (const uint4*)g_qh;
        const uint4* Ql4 = (const uint4*)g_ql;
#pragma unroll
        for (int i = 0; i < 4; i++) {
            int idx = t + i * 256;
            int comp = idx >> 9, rem = idx & 511;
            int m = rem >> 2, k4 = rem & 3;
            cp_async16(sb + (comp ? QL_OFF : QH_OFF) + m * 80 + k4 * 16,
                       (comp ? Ql4 : Qh4) + (size_t)(b * Q_ + q0 + m) * 32 + h * 4 + k4);
        }
    }
    stage_kv(0, 0);
    stage_kv(1, 1);
    CP_WAIT(1);
    __syncthreads();

    uint32_t qh[2][4], ql[2][4];
    {
        uint32_t roff = (uint32_t)(w * 16 + (lane & 15)) * 80 + ((lane >> 4) * 16);
#pragma unroll
        for (int ks = 0; ks < 2; ks++) {
            ldsm_x4(qh[ks][0], qh[ks][1], qh[ks][2], qh[ks][3], sb + QH_OFF + roff + ks * 32);
            ldsm_x4(ql[ks][0], ql[ks][1], ql[ks][2], ql[ks][3], sb + QL_OFF + roff + ks * 32);
        }
    }

    const int qr1 = q0 + w * 16 + (lane >> 2);
    const int cb  = (lane & 3) * 2;
    const float* brow1 = bias + ((size_t)b * Q_ + qr1) * K_;
    const float* brow2 = brow1 + 8 * K_;
    const float* nrow1 = nb + ((size_t)h * Q_ + qr1) * K_;
    const float* nrow2 = nrow1 + 8 * K_;

    float m1 = -3.0e38f, m2 = -3.0e38f, l1 = 0.f, l2 = 0.f;
    float o[4][4];
#pragma unroll
    for (int i = 0; i < 4; i++)
#pragma unroll
        for (int e = 0; e < 4; e++) o[i][e] = 0.f;

    for (int kc = 0; kc < 8; kc++) {
        const int kbase = kc * 64;
        const uint32_t base = sb + ST_BASE + (kc & 1) * A_STAGE;

        float bsum[8][4];
#pragma unroll
        for (int nt = 0; nt < 8; nt++) {
            int kcol = kbase + nt * 8 + cb;
            float2 b1 = *(const float2*)&brow1[kcol];
            float2 n1 = *(const float2*)&nrow1[kcol];
            float2 b2 = *(const float2*)&brow2[kcol];
            float2 n2 = *(const float2*)&nrow2[kcol];
            bsum[nt][0] = b1.x + n1.x; bsum[nt][1] = b1.y + n1.y;
            bsum[nt][2] = b2.x + n2.x; bsum[nt][3] = b2.y + n2.y;
        }

        float s[8][4];
#pragma unroll
        for (int j = 0; j < 8; j++)
#pragma unroll
            for (int e = 0; e < 4; e++) s[j][e] = 0.f;
#pragma unroll
        for (int ks = 0; ks < 2; ks++) {
            uint32_t bh[8][2], bl[8][2];
#pragma unroll
            for (int p = 0; p < 4; p++) {
                uint32_t nrow = (uint32_t)(p * 16 + ((lane >> 4) << 3) + (lane & 7));
                uint32_t addr = nrow * 80 + ((lane >> 3) & 1) * 16 + ks * 32;
                uint32_t a0, a1, a2, a3;
                ldsm_x4(a0, a1, a2, a3, base + 0 + addr);
                bh[p * 2][0] = a0; bh[p * 2][1] = a1;
                bh[p * 2 + 1][0] = a2; bh[p * 2 + 1][1] = a3;
                ldsm_x4(a0, a1, a2, a3, base + 5120 + addr);
                bl[p * 2][0] = a0; bl[p * 2][1] = a1;
                bl[p * 2 + 1][0] = a2; bl[p * 2 + 1][1] = a3;
            }
#pragma unroll
            for (int nt = 0; nt < 8; nt++) {
                mma_bf16(s[nt], qh[ks], bh[nt]);
                mma_bf16(s[nt], qh[ks], bl[nt]);
                mma_bf16(s[nt], ql[ks], bh[nt]);
            }
        }

#pragma unroll
        for (int nt = 0; nt < 8; nt++) {
            s[nt][0] += bsum[nt][0]; s[nt][1] += bsum[nt][1];
            s[nt][2] += bsum[nt][2]; s[nt][3] += bsum[nt][3];
        }

        float mc1 = s[0][0], mc2 = s[0][2];
#pragma unroll
        for (int nt = 0; nt < 8; nt++) {
            mc1 = fmaxf(mc1, fmaxf(s[nt][0], s[nt][1]));
            mc2 = fmaxf(mc2, fmaxf(s[nt][2], s[nt][3]));
        }
        mc1 = fmaxf(mc1, __shfl_xor_sync(0xffffffffu, mc1, 1));
        mc1 = fmaxf(mc1, __shfl_xor_sync(0xffffffffu, mc1, 2));
        mc2 = fmaxf(mc2, __shfl_xor_sync(0xffffffffu, mc2, 1));
        mc2 = fmaxf(mc2, __shfl_xor_sync(0xffffffffu, mc2, 2));
        float mn1 = fmaxf(m1, mc1), mn2 = fmaxf(m2, mc2);
        float sc1 = __expf(m1 - mn1), sc2 = __expf(m2 - mn2);
        l1 *= sc1; l2 *= sc2;
#pragma unroll
        for (int nt = 0; nt < 4; nt++) {
            o[nt][0] *= sc1; o[nt][1] *= sc1;
            o[nt][2] *= sc2; o[nt][3] *= sc2;
        }
        m1 = mn1; m2 = mn2;

        float ps1 = 0.f, ps2 = 0.f;
        uint32_t aph[4][4], apl[4][4];
#pragma unroll
        for (int nt = 0; nt < 8; nt++) {
            float p0 = __expf(s[nt][0] - mn1);
            float p1 = __expf(s[nt][1] - mn1);
            float p2 = __expf(s[nt][2] - mn2);
            float p3 = __expf(s[nt][3] - mn2);
            ps1 += p0 + p1; ps2 += p2 + p3;
            int kp = nt >> 1, hi = (nt & 1) << 1;
            split2f(p0, p1, aph[kp][hi], apl[kp][hi]);
            split2f(p2, p3, aph[kp][hi + 1], apl[kp][hi + 1]);
        }
        ps1 += __shfl_xor_sync(0xffffffffu, ps1, 1);
        ps1 += __shfl_xor_sync(0xffffffffu, ps1, 2);
        ps2 += __shfl_xor_sync(0xffffffffu, ps2, 1);
        ps2 += __shfl_xor_sync(0xffffffffu, ps2, 2);
        l1 += ps1; l2 += ps2;

#pragma unroll
        for (int kp = 0; kp < 4; kp++) {
            uint32_t bvh[4][2], bvl[4][2];
            uint32_t g = lane >> 3;
            uint32_t rbase = (uint32_t)(kp * 16 + ((g & 1) << 3) + (lane & 7)) * 80 + ((g >> 1) * 16);
#pragma unroll
            for (int nh = 0; nh < 2; nh++) {
                uint32_t a0, a1, a2, a3;
                ldsm_x4t(a0, a1, a2, a3, base + 10240 + rbase + nh * 32);
                bvh[nh * 2][0] = a0; bvh[nh * 2][1] = a1;
                bvh[nh * 2 + 1][0] = a2; bvh[nh * 2 + 1][1] = a3;
                ldsm_x4t(a0, a1, a2, a3, base + 15360 + rbase + nh * 32);
                bvl[nh * 2][0] = a0; bvl[nh * 2][1] = a1;
                bvl[nh * 2 + 1][0] = a2; bvl[nh * 2 + 1][1] = a3;
            }
#pragma unroll
            for (int nt = 0; nt < 4; nt++) {
                mma_bf16(o[nt], aph[kp], bvh[nt]);
                mma_bf16(o[nt], aph[kp], bvl[nt]);
                mma_bf16(o[nt], apl[kp], bvh[nt]);
            }
        }

        if (kc == 7) break;
        __syncthreads();
        if (kc + 2 < 8) { stage_kv(kc + 2, kc & 1); CP_WAIT(1); }
        else            { CP_WAIT(0); }
        __syncthreads();
    }

    float inv1 = 1.f / l1, inv2 = 1.f / l2;
    const size_t rg1 = (size_t)(b * Q_ + qr1);
    const size_t rg2 = rg1 + 8;
#pragma unroll
    for (int nt = 0; nt < 4; nt++) {
        int col = h * 32 + nt * 8 + cb;
        float2 gg1 = *(const float2*)&g_gate[rg1 * 256 + col];
        float2 gg2 = *(const float2*)&g_gate[rg2 * 256 + col];
        float v0 = o[nt][0] * inv1 * gg1.x;
        float v1 = o[nt][1] * inv1 * gg1.y;
        float v2 = o[nt][2] * inv2 * gg2.x;
        float v3 = o[nt][3] * inv2 * gg2.y;
        uint32_t h0, l0, h1, lw1;
        split2f(v0, v1, h0, l0);
        split2f(v2, v3, h1, lw1);
        g_wah[rg1 * 128 + (col >> 1)] = h0;
        g_wal[rg1 * 128 + (col >> 1)] = l0;
        g_wah[rg2 * 128 + (col >> 1)] = h1;
        g_wal[rg2 * 128 + (col >> 1)] = lw1;
    }
}

// ---------------------------------------------------------------------------
extern "C" void kernel_launch(void* const* d_in, const int* in_sizes, int n_in,
                              void* d_out, int out_size)
{
    const float* q_data = (const float*)d_in[0];
    const float* m_data = (const float*)d_in[1];
    const float* bias   = (const float*)d_in[2];
    const float* nb     = (const float*)d_in[3];
    const float* qw     = (const float*)d_in[4];
    const float* kw     = (const float*)d_in[5];
    const float* vw     = (const float*)d_in[6];
    const float* gw     = (const float*)d_in[7];
    const float* gb     = (const float*)d_in[8];
    const float* ow     = (const float*)d_in[9];
    const float* ob     = (const float*)d_in[10];
    float* out = (float*)d_out;

    cudaFuncSetAttribute(gemm8_kernel, cudaFuncAttributeMaxDynamicSharedMemorySize, 2 * G8_STAGE);
    cudaFuncSetAttribute(gemm_kernel, cudaFuncAttributeMaxDynamicSharedMemorySize, 2 * G_STAGE);
    cudaFuncSetAttribute(attn_kernel, cudaFuncAttributeMaxDynamicSharedMemorySize, ST_BASE + 2 * A_STAGE);

    prep_all<<<8272, 256>>>(q_data, m_data, qw, kw, vw, gw, ow);

    gemm8_kernel<<<dim3(128, 2, 4), 256, 2 * G8_STAGE>>>(gb);

    attn_kernel<<<dim3(H_, Q_ / 128, B_), 256, ST_BASE + 2 * A_STAGE>>>(bias, nb);

    gemm_kernel<<<dim3(128, 2), 256, 2 * G_STAGE>>>(ob, out);
}

// round 17
// speedup vs baseline: 1.0908x; 1.0908x over previous
#include <cuda_runtime.h>
#include <cuda_bf16.h>
#include <cstdint>
#include <math.h>

#define B_   32
#define Q_   512
#define K_   512
#define H_   8

#define M_TOTAL (B_*Q_)           // 16384
#define ACT_ELEMS (M_TOTAL*256)
#define ACT_U4  (ACT_ELEMS*2/16)
#define WT_U4   (5*256*256*2/16)

// inputs split to bf16 hi/lo (row-major [m][256])
__device__ uint4 g_qd_hi[ACT_U4];
__device__ uint4 g_qd_lo[ACT_U4];
__device__ uint4 g_md_hi[ACT_U4];
__device__ uint4 g_md_lo[ACT_U4];
__device__ uint4 g_wt_hi[WT_U4];   // 5 weight matrices, [n][k]
__device__ uint4 g_wt_lo[WT_U4];

// projection outputs, bf16 hi/lo as uint32 pairs: [16384][128]
__device__ uint32_t g_qh[M_TOTAL*128];
__device__ uint32_t g_ql[M_TOTAL*128];
__device__ uint32_t g_kh[M_TOTAL*128];
__device__ uint32_t g_kl[M_TOTAL*128];
__device__ uint32_t g_vh[M_TOTAL*128];
__device__ uint32_t g_vl[M_TOTAL*128];
__device__ float    g_gate[M_TOTAL*256];
// attention output, bf16 hi/lo
__device__ uint32_t g_wah[M_TOTAL*128];
__device__ uint32_t g_wal[M_TOTAL*128];

__device__ __forceinline__ uint32_t smem_u32(const void* p) {
    uint32_t a;
    asm("{ .reg .u64 t; cvta.to.shared.u64 t, %1; cvt.u32.u64 %0, t; }" : "=r"(a) : "l"(p));
    return a;
}
__device__ __forceinline__ uint32_t pack2(float a, float b) {
    __nv_bfloat162 h = __floats2bfloat162_rn(a, b);
    return *(uint32_t*)&h;
}
__device__ __forceinline__ void split2(float x, float y, uint32_t& hi, uint32_t& lo) {
    __nv_bfloat16 bx = __float2bfloat16_rn(x), by = __float2bfloat16_rn(y);
    __nv_bfloat162 h2; h2.x = bx; h2.y = by;
    hi = *(uint32_t*)&h2;
    lo = pack2(x - __bfloat162float(bx), y - __bfloat162float(by));
}
// truncation split: hi = top 16 bits (RZ), lo compensates exactly
__device__ __forceinline__ void split2f(float x, float y, uint32_t& hi, uint32_t& lo) {
    uint32_t xu = __float_as_uint(x), yu = __float_as_uint(y);
    hi = __byte_perm(xu, yu, 0x7632);
    float xh = __uint_as_float(xu & 0xFFFF0000u);
    float yh = __uint_as_float(yu & 0xFFFF0000u);
    lo = pack2(x - xh, y - yh);
}
__device__ __forceinline__ void ldsm_x4(uint32_t& r0, uint32_t& r1, uint32_t& r2, uint32_t& r3, uint32_t addr) {
    asm volatile("ldmatrix.sync.aligned.m8n8.x4.shared.b16 {%0,%1,%2,%3}, [%4];"
                 : "=r"(r0), "=r"(r1), "=r"(r2), "=r"(r3) : "r"(addr));
}
__device__ __forceinline__ void ldsm_x4t(uint32_t& r0, uint32_t& r1, uint32_t& r2, uint32_t& r3, uint32_t addr) {
    asm volatile("ldmatrix.sync.aligned.m8n8.x4.trans.shared.b16 {%0,%1,%2,%3}, [%4];"
                 : "=r"(r0), "=r"(r1), "=r"(r2), "=r"(r3) : "r"(addr));
}
__device__ __forceinline__ void mma_bf16(float* c, const uint32_t* a, const uint32_t* b) {
    asm volatile("mma.sync.aligned.m16n8k16.row.col.f32.bf16.bf16.f32 "
                 "{%0,%1,%2,%3}, {%4,%5,%6,%7}, {%8,%9}, {%0,%1,%2,%3};"
                 : "+f"(c[0]), "+f"(c[1]), "+f"(c[2]), "+f"(c[3])
                 : "r"(a[0]), "r"(a[1]), "r"(a[2]), "r"(a[3]), "r"(b[0]), "r"(b[1]));
}
__device__ __forceinline__ void cp_async16(uint32_t dst, const void* src) {
    asm volatile("cp.async.cg.shared.global [%0], [%1], 16;" :: "r"(dst), "l"(src));
}
#define CP_COMMIT() asm volatile("cp.async.commit_group;" ::: "memory")
#define CP_WAIT(n)  asm volatile("cp.async.wait_group %0;" :: "n"(n) : "memory")

// ---------------- fused prep: activations + weights in one launch ----------
__global__ __launch_bounds__(256)
void prep_all(const float* __restrict__ q_data, const float* __restrict__ m_data,
              const float* __restrict__ qw, const float* __restrict__ kw,
              const float* __restrict__ vw, const float* __restrict__ gw,
              const float* __restrict__ ow)
{
    const int bid = blockIdx.x;
    const int t = threadIdx.x;
    if (bid < 8192) {
        int sel = bid >> 12;
        int i = (bid & 4095) * 256 + t;
        uint2* hi = (sel == 0) ? (uint2*)g_qd_hi : (uint2*)g_md_hi;
        uint2* lo = (sel == 0) ? (uint2*)g_qd_lo : (uint2*)g_md_lo;
        const float4* s4 = (const float4*)((sel == 0) ? q_data : m_data);
        float4 v = s4[i];
        uint2 ho, lw;
        split2(v.x, v.y, ho.x, lw.x);
        split2(v.z, v.w, ho.y, lw.y);
        hi[i] = ho; lo[i] = lw;
        return;
    }
    __shared__ float s[64][65];
    const int wid = bid - 8192;
    const int z  = wid >> 4;
    const int kx = (wid >> 2) & 3;
    const int ny = wid & 3;
    const float* W = (z == 0) ? qw : (z == 1) ? kw : (z == 2) ? vw : (z == 3) ? gw : ow;
    const int k0 = kx * 64;
    const int n0 = ny * 64;
#pragma unroll
    for (int i = 0; i < 4; i++) {
        int idx = t + i * 256;
        int k = idx >> 4, n4 = idx & 15;
        float4 v = *(const float4*)&W[(size_t)(k0 + k) * 256 + n0 + n4 * 4];
        s[n4 * 4 + 0][k] = v.x; s[n4 * 4 + 1][k] = v.y;
        s[n4 * 4 + 2][k] = v.z; s[n4 * 4 + 3][k] = v.w;
    }
    __syncthreads();
    uint2* Hi = (uint2*)g_wt_hi;
    uint2* Lo = (uint2*)g_wt_lo;
#pragma unroll
    for (int i = 0; i < 4; i++) {
        int idx = t + i * 256;
        int n = idx >> 4, k4 = idx & 15;
        uint2 ho, lw;
        split2(s[n][k4 * 4 + 0], s[n][k4 * 4 + 1], ho.x, lw.x);
        split2(s[n][k4 * 4 + 2], s[n][k4 * 4 + 3], ho.y, lw.y);
        int eo = (z * 65536 + (n0 + n) * 256 + k0 + k4 * 4) >> 2;
        Hi[eo] = ho; Lo[eo] = lw;
    }
}

// ---------------- GEMM: 128(M) x 128(N) tile, K=256, hi/lo, cp.async x2 ----
#define AH_OFF 0
#define AL_OFF 10240
#define BH_OFF 20480
#define BL_OFF 30720
#define G_STAGE 40960

__global__ __launch_bounds__(256, 2)
void gemm_kernel(int job, const float* __restrict__ gb,
                 const float* __restrict__ ob, float* __restrict__ dout)
{
    extern __shared__ __align__(128) char smg[];
    const uint32_t sb = smem_u32(smg);
    const int t = threadIdx.x, w = t >> 5, lane = t & 31;
    const int mw = w >> 1, nw = w & 1;          // 4(M) x 2(N) warps
    const int mode = (job == 0) ? (int)blockIdx.z : 4;
    const int m0 = blockIdx.x * 128;
    const int n0 = blockIdx.y * 128;

    const uint4 *Ah, *Al;
    uint32_t *Oh = nullptr, *Ol = nullptr;
    float* Of = nullptr;
    if (mode == 0)      { Ah = g_qd_hi; Al = g_qd_lo; Oh = g_qh; Ol = g_ql; }
    else if (mode == 1) { Ah = g_md_hi; Al = g_md_lo; Oh = g_kh; Ol = g_kl; }
    else if (mode == 2) { Ah = g_md_hi; Al = g_md_lo; Oh = g_vh; Ol = g_vl; }
    else if (mode == 3) { Ah = g_qd_hi; Al = g_qd_lo; Of = g_gate; }
    else                { Ah = (const uint4*)g_wah; Al = (const uint4*)g_wal; Of = dout; }
    const uint4* Wh = g_wt_hi + mode * 8192;
    const uint4* Wl = g_wt_lo + mode * 8192;

    auto stage = [&](int kc, int buf) {
        uint32_t base = sb + buf * G_STAGE;
#pragma unroll
        for (int i = 0; i < 4; i++) {            // A: 128 rows x 32 bf16 x2
            int idx = t + i * 256;
            int comp = idx >> 9, rem = idx & 511;
            int m = rem >> 2, k4 = rem & 3;
            const uint4* src = (comp ? Al : Ah) + (size_t)(m0 + m) * 32 + kc * 4 + k4;
            cp_async16(base + (comp ? AL_OFF : AH_OFF) + m * 80 + k4 * 16, src);
        }
#pragma unroll
        for (int i = 0; i < 4; i++) {            // B: 128 n-rows x 32 bf16 x2
            int idx = t + i * 256;
            int comp = idx >> 9, rem = idx & 511;
            int n = rem >> 2, k4 = rem & 3;
            const uint4* src = (comp ? Wl : Wh) + (size_t)(n0 + n) * 32 + kc * 4 + k4;
            cp_async16(base + (comp ? BL_OFF : BH_OFF) + n * 80 + k4 * 16, src);
        }
        CP_COMMIT();
    };

    float c[2][8][4];
#pragma unroll
    for (int i = 0; i < 2; i++)
#pragma unroll
        for (int j = 0; j < 8; j++)
#pragma unroll
            for (int e = 0; e < 4; e++) c[i][j][e] = 0.f;

    stage(0, 0);
    stage(1, 1);
    CP_WAIT(1);
    __syncthreads();

    for (int kc = 0; kc < 8; kc++) {
        const uint32_t base = sb + (kc & 1) * G_STAGE;
#pragma unroll
        for (int ks = 0; ks < 2; ks++) {
            uint32_t ah[2][4], al[2][4];
#pragma unroll
            for (int mt = 0; mt < 2; mt++) {
                uint32_t roff = (uint32_t)(mw * 32 + mt * 16 + (lane & 15)) * 80 + ((lane >> 4) * 16) + ks * 32;
                ldsm_x4(ah[mt][0], ah[mt][1], ah[mt][2], ah[mt][3], base + AH_OFF + roff);
                ldsm_x4(al[mt][0], al[mt][1], al[mt][2], al[mt][3], base + AL_OFF + roff);
            }
            uint32_t bh[8][2], bl[8][2];
#pragma unroll
            for (int p = 0; p < 4; p++) {
                uint32_t nrow = (uint32_t)(nw * 64 + p * 16 + ((lane >> 4) << 3) + (lane & 7));
                uint32_t addr = nrow * 80 + ((lane >> 3) & 1) * 16 + ks * 32;
                uint32_t a0, a1, a2, a3;
                ldsm_x4(a0, a1, a2, a3, base + BH_OFF + addr);
                bh[p * 2][0] = a0; bh[p * 2][1] = a1;
                bh[p * 2 + 1][0] = a2; bh[p * 2 + 1][1] = a3;
                ldsm_x4(a0, a1, a2, a3, base + BL_OFF + addr);
                bl[p * 2][0] = a0; bl[p * 2][1] = a1;
                bl[p * 2 + 1][0] = a2; bl[p * 2 + 1][1] = a3;
            }
#pragma unroll
            for (int mt = 0; mt < 2; mt++)
#pragma unroll
                for (int nt = 0; nt < 8; nt++) {
                    mma_bf16(c[mt][nt], ah[mt], bh[nt]);
                    mma_bf16(c[mt][nt], ah[mt], bl[nt]);
                    mma_bf16(c[mt][nt], al[mt], bh[nt]);
                }
        }
        if (kc == 7) break;
        __syncthreads();                  // everyone done reading buf kc&1
        if (kc + 2 < 8) { stage(kc + 2, kc & 1); CP_WAIT(1); }
        else            { CP_WAIT(0); }
        __syncthreads();                  // chunk kc+1 visible to all
    }

    const float s_q = 0.17677669529663687f;
#pragma unroll
    for (int mt = 0; mt < 2; mt++) {
#pragma unroll
        for (int nt = 0; nt < 8; nt++) {
            int row = m0 + mw * 32 + mt * 16 + (lane >> 2);
            int col = n0 + nw * 64 + nt * 8 + (lane & 3) * 2;
            float2 v0 = make_float2(c[mt][nt][0], c[mt][nt][1]);
            float2 v1 = make_float2(c[mt][nt][2], c[mt][nt][3]);
            if (mode == 0) { v0.x *= s_q; v0.y *= s_q; v1.x *= s_q; v1.y *= s_q; }
            if (mode <= 2) {
                uint32_t h0, l0, h1, l1;
                split2(v0.x, v0.y, h0, l0);
                split2(v1.x, v1.y, h1, l1);
                Oh[(size_t)row * 128 + (col >> 1)] = h0;
                Ol[(size_t)row * 128 + (col >> 1)] = l0;
                Oh[(size_t)(row + 8) * 128 + (col >> 1)] = h1;
                Ol[(size_t)(row + 8) * 128 + (col >> 1)] = l1;
            } else if (mode == 3) {
                float2 g2 = *(const float2*)&gb[col];
                v0.x = 1.f / (1.f + __expf(-(v0.x + g2.x)));
                v0.y = 1.f / (1.f + __expf(-(v0.y + g2.y)));
                v1.x = 1.f / (1.f + __expf(-(v1.x + g2.x)));
                v1.y = 1.f / (1.f + __expf(-(v1.y + g2.y)));
                *(float2*)&Of[(size_t)row * 256 + col] = v0;
                *(float2*)&Of[(size_t)(row + 8) * 256 + col] = v1;
            } else {
                float2 g2 = *(const float2*)&ob[col];
                v0.x += g2.x; v0.y += g2.y; v1.x += g2.x; v1.y += g2.y;
                *(float2*)&Of[(size_t)row * 256 + col] = v0;
                *(float2*)&Of[(size_t)(row + 8) * 256 + col] = v1;
            }
        }
    }
}

// ---------------- tensor-core flash attention, cp.async x2 -----------------
// round-13 structure; QK drops the q_hi*k_lo pass -> no KL plane staged.
// stage layout: KH 0, VH 5120, VL 10240  (15360 B per stage)
#define QH_OFF 0
#define QL_OFF 10240
#define ST_BASE 20480
#define A_STAGE 15360

__global__ __launch_bounds__(256, 2)
void attn_kernel(const float* __restrict__ bias,
                 const float* __restrict__ nb)
{
    extern __shared__ __align__(128) char sma[];
    const uint32_t sb = smem_u32(sma);
    const int h  = blockIdx.x;
    const int q0 = blockIdx.y * 128;
    const int b  = blockIdx.z;
    const int t = threadIdx.x, w = t >> 5, lane = t & 31;

    const uint4* K3[3] = {(const uint4*)g_kh, (const uint4*)g_vh, (const uint4*)g_vl};
    const uint32_t dstoff[3] = {0, 5120, 10240};

    auto stage_kv = [&](int kc, int buf) {
        uint32_t base = sb + ST_BASE + buf * A_STAGE;
        int r = t >> 2, k4 = t & 3;
#pragma unroll
        for (int i = 0; i < 3; i++) {
            const uint4* src = K3[i] + (size_t)(b * K_ + kc * 64 + r) * 32 + h * 4 + k4;
            cp_async16(base + dstoff[i] + r * 80 + k4 * 16, src);
        }
        CP_COMMIT();
    };

    // Q tile [128 rows][32 bf16] hi/lo via cp.async (group 0 with KV chunk 0)
    {
        const uint4* Qh4 = (const uint4*)g_qh;
        const uint4* Ql4 = (const uint4*)g_ql;
#pragma unroll
        for (int i = 0; i < 4; i++) {
            int idx = t + i * 256;
            int comp = idx >> 9, rem = idx & 511;
            int m = rem >> 2, k4 = rem & 3;
            const uint4* src = (comp ? Ql4 : Qh4) + (size_t)(b * Q_ + q0 + m) * 32 + h * 4 + k4;
            cp_async16(sb + (comp ? QL_OFF : QH_OFF) + m * 80 + k4 * 16, src);
        }
    }
    stage_kv(0, 0);          // group 0 = Q + KV0
    stage_kv(1, 1);          // group 1
    CP_WAIT(1);              // Q + KV0 ready
    __syncthreads();

    uint32_t qh[2][4], ql[2][4];
    {
        uint32_t roff = (uint32_t)(w * 16 + (lane & 15)) * 80 + ((lane >> 4) * 16);
#pragma unroll
        for (int ks = 0; ks < 2; ks++) {
            ldsm_x4(qh[ks][0], qh[ks][1], qh[ks][2], qh[ks][3], sb + QH_OFF + roff + ks * 32);
            ldsm_x4(ql[ks][0], ql[ks][1], ql[ks][2], ql[ks][3], sb + QL_OFF + roff + ks * 32);
        }
    }

    const int qr1 = q0 + w * 16 + (lane >> 2);
    const int cb  = (lane & 3) * 2;
    const float* brow1 = bias + ((size_t)b * Q_ + qr1) * K_;
    const float* brow2 = brow1 + 8 * K_;
    const float* nrow1 = nb + ((size_t)h * Q_ + qr1) * K_;
    const float* nrow2 = nrow1 + 8 * K_;

    float m1 = -3.0e38f, m2 = -3.0e38f, l1 = 0.f, l2 = 0.f;
    float o[4][4];
#pragma unroll
    for (int i = 0; i < 4; i++)
#pragma unroll
        for (int e = 0; e < 4; e++) o[i][e] = 0.f;

    for (int kc = 0; kc < 8; kc++) {
        const int kbase = kc * 64;
        const uint32_t base = sb + ST_BASE + (kc & 1) * A_STAGE;

        // ---- hoisted bias+nb loads: LDG latency overlaps the QK mmas -------
        float bsum[8][4];
#pragma unroll
        for (int nt = 0; nt < 8; nt++) {
            int kcol = kbase + nt * 8 + cb;
            float2 b1 = *(const float2*)&brow1[kcol];
            float2 n1 = *(const float2*)&nrow1[kcol];
            float2 b2 = *(const float2*)&brow2[kcol];
            float2 n2 = *(const float2*)&nrow2[kcol];
            bsum[nt][0] = b1.x + n1.x; bsum[nt][1] = b1.y + n1.y;
            bsum[nt][2] = b2.x + n2.x; bsum[nt][3] = b2.y + n2.y;
        }

        // ---- S = q k^T : (qh+ql) * kh  (q_hi*k_lo term dropped, ~2^-9) ----
        float s[8][4];
#pragma unroll
        for (int j = 0; j < 8; j++)
#pragma unroll
            for (int e = 0; e < 4; e++) s[j][e] = 0.f;
#pragma unroll
        for (int ks = 0; ks < 2; ks++) {
            uint32_t bh[8][2];
#pragma unroll
            for (int p = 0; p < 4; p++) {
                uint32_t nrow = (uint32_t)(p * 16 + ((lane >> 4) << 3) + (lane & 7));
                uint32_t addr = nrow * 80 + ((lane >> 3) & 1) * 16 + ks * 32;
                uint32_t a0, a1, a2, a3;
                ldsm_x4(a0, a1, a2, a3, base + 0 + addr);        // KH
                bh[p * 2][0] = a0; bh[p * 2][1] = a1;
                bh[p * 2 + 1][0] = a2; bh[p * 2 + 1][1] = a3;
            }
#pragma unroll
            for (int nt = 0; nt < 8; nt++) {
                mma_bf16(s[nt], qh[ks], bh[nt]);
                mma_bf16(s[nt], ql[ks], bh[nt]);
            }
        }

        // ---- + combined bias ------------------------------------------------
#pragma unroll
        for (int nt = 0; nt < 8; nt++) {
            s[nt][0] += bsum[nt][0]; s[nt][1] += bsum[nt][1];
            s[nt][2] += bsum[nt][2]; s[nt][3] += bsum[nt][3];
        }

        // ---- online softmax -------------------------------------------------
        float mc1 = s[0][0], mc2 = s[0][2];
#pragma unroll
        for (int nt = 0; nt < 8; nt++) {
            mc1 = fmaxf(mc1, fmaxf(s[nt][0], s[nt][1]));
            mc2 = fmaxf(mc2, fmaxf(s[nt][2], s[nt][3]));
        }
        mc1 = fmaxf(mc1, __shfl_xor_sync(0xffffffffu, mc1, 1));
        mc1 = fmaxf(mc1, __shfl_xor_sync(0xffffffffu, mc1, 2));
        mc2 = fmaxf(mc2, __shfl_xor_sync(0xffffffffu, mc2, 1));
        mc2 = fmaxf(mc2, __shfl_xor_sync(0xffffffffu, mc2, 2));
        float mn1 = fmaxf(m1, mc1), mn2 = fmaxf(m2, mc2);
        float sc1 = __expf(m1 - mn1), sc2 = __expf(m2 - mn2);
        l1 *= sc1; l2 *= sc2;
#pragma unroll
        for (int nt = 0; nt < 4; nt++) {
            o[nt][0] *= sc1; o[nt][1] *= sc1;
            o[nt][2] *= sc2; o[nt][3] *= sc2;
        }
        m1 = mn1; m2 = mn2;

        float ps1 = 0.f, ps2 = 0.f;
        uint32_t aph[4][4], apl[4][4];
#pragma unroll
        for (int nt = 0; nt < 8; nt++) {
            float p0 = __expf(s[nt][0] - mn1);
            float p1 = __expf(s[nt][1] - mn1);
            float p2 = __expf(s[nt][2] - mn2);
            float p3 = __expf(s[nt][3] - mn2);
            ps1 += p0 + p1; ps2 += p2 + p3;
            int kp = nt >> 1, hi = (nt & 1) << 1;
            split2f(p0, p1, aph[kp][hi], apl[kp][hi]);
            split2f(p2, p3, aph[kp][hi + 1], apl[kp][hi + 1]);
        }
        ps1 += __shfl_xor_sync(0xffffffffu, ps1, 1);
        ps1 += __shfl_xor_sync(0xffffffffu, ps1, 2);
        ps2 += __shfl_xor_sync(0xffffffffu, ps2, 1);
        ps2 += __shfl_xor_sync(0xffffffffu, ps2, 2);
        l1 += ps1; l2 += ps2;

        // ---- o += P V (full hi/lo 3-pass, error hits output directly) ------
#pragma unroll
        for (int kp = 0; kp < 4; kp++) {
            uint32_t bvh[4][2], bvl[4][2];
            uint32_t g = lane >> 3;
            uint32_t rbase = (uint32_t)(kp * 16 + ((g & 1) << 3) + (lane & 7)) * 80 + ((g >> 1) * 16);
#pragma unroll
            for (int nh = 0; nh < 2; nh++) {
                uint32_t a0, a1, a2, a3;
                ldsm_x4t(a0, a1, a2, a3, base + 5120 + rbase + nh * 32);    // VH
                bvh[nh * 2][0] = a0; bvh[nh * 2][1] = a1;
                bvh[nh * 2 + 1][0] = a2; bvh[nh * 2 + 1][1] = a3;
                ldsm_x4t(a0, a1, a2, a3, base + 10240 + rbase + nh * 32);   // VL
                bvl[nh * 2][0] = a0; bvl[nh * 2][1] = a1;
                bvl[nh * 2 + 1][0] = a2; bvl[nh * 2 + 1][1] = a3;
            }
#pragma unroll
            for (int nt = 0; nt < 4; nt++) {
                mma_bf16(o[nt], aph[kp], bvh[nt]);
                mma_bf16(o[nt], aph[kp], bvl[nt]);
                mma_bf16(o[nt], apl[kp], bvh[nt]);
            }
        }

        if (kc == 7) break;
        __syncthreads();                       // done reading stage kc&1
        if (kc + 2 < 8) { stage_kv(kc + 2, kc & 1); CP_WAIT(1); }
        else            { CP_WAIT(0); }
        __syncthreads();                       // chunk kc+1 visible
    }

    // ---- epilogue: normalize, gate, write wa hi/lo -------------------------
    float inv1 = 1.f / l1, inv2 = 1.f / l2;
    const size_t rg1 = (size_t)(b * Q_ + qr1);
    const size_t rg2 = rg1 + 8;
#pragma unroll
    for (int nt = 0; nt < 4; nt++) {
        int col = h * 32 + nt * 8 + cb;
        float2 gg1 = *(const float2*)&g_gate[rg1 * 256 + col];
        float2 gg2 = *(const float2*)&g_gate[rg2 * 256 + col];
        float v0 = o[nt][0] * inv1 * gg1.x;
        float v1 = o[nt][1] * inv1 * gg1.y;
        float v2 = o[nt][2] * inv2 * gg2.x;
        float v3 = o[nt][3] * inv2 * gg2.y;
        uint32_t h0, l0, h1, lw1;
        split2f(v0, v1, h0, l0);
        split2f(v2, v3, h1, lw1);
        g_wah[rg1 * 128 + (col >> 1)] = h0;
        g_wal[rg1 * 128 + (col >> 1)] = l0;
        g_wah[rg2 * 128 + (col >> 1)] = h1;
        g_wal[rg2 * 128 + (col >> 1)] = lw1;
    }
}

// ---------------------------------------------------------------------------
extern "C" void kernel_launch(void* const* d_in, const int* in_sizes, int n_in,
                              void* d_out, int out_size)
{
    const float* q_data = (const float*)d_in[0];
    const float* m_data = (const float*)d_in[1];
    const float* bias   = (const float*)d_in[2];
    const float* nb     = (const float*)d_in[3];
    const float* qw     = (const float*)d_in[4];
    const float* kw     = (const float*)d_in[5];
    const float* vw     = (const float*)d_in[6];
    const float* gw     = (const float*)d_in[7];
    const float* gb     = (const float*)d_in[8];
    const float* ow     = (const float*)d_in[9];
    const float* ob     = (const float*)d_in[10];
    float* out = (float*)d_out;

    cudaFuncSetAttribute(gemm_kernel, cudaFuncAttributeMaxDynamicSharedMemorySize, 2 * G_STAGE);
    cudaFuncSetAttribute(attn_kernel, cudaFuncAttributeMaxDynamicSharedMemorySize, ST_BASE + 2 * A_STAGE);

    prep_all<<<8272, 256>>>(q_data, m_data, qw, kw, vw, gw, ow);

    gemm_kernel<<<dim3(128, 2, 4), 256, 2 * G_STAGE>>>(0, gb, ob, nullptr);

    attn_kernel<<<dim3(H_, Q_ / 128, B_), 256, ST_BASE + 2 * A_STAGE>>>(bias, nb);

    gemm_kernel<<<dim3(128, 2), 256, 2 * G_STAGE>>>(1, gb, ob, out);
}